// round 1
// baseline (speedup 1.0000x reference)
#include <cuda_runtime.h>
#include <cuda_bf16.h>

#define BCH   10
#define HH    320
#define WW    1024
#define PTS   500
#define DENSE 2000
#define KMEAN 10
#define NPTS  (BCH * PTS)

// One warp per center point. Samples live in registers (63 per lane).
__global__ __launch_bounds__(256, 2)
void rsbsp_kernel(const float* __restrict__ disp,
                  const float* __restrict__ fore,
                  const int*   __restrict__ cxs,
                  const int*   __restrict__ cys,
                  const int*   __restrict__ bxs,
                  const int*   __restrict__ bys,
                  float*       __restrict__ out)
{
    const int gwarp = (blockIdx.x * blockDim.x + threadIdx.x) >> 5;
    const int lane  = threadIdx.x & 31;
    if (gwarp >= NPTS) return;

    const int n    = gwarp;
    const int chan = n / PTS;
    const int cx   = cxs[n];
    const int cy   = cys[n];
    const float* dch = disp + (size_t)chan * (HH * WW);
    const float* fch = fore + (size_t)chan * (HH * WW);

    // ---- validRow: maxpool3x3(|sobel_x(forepred)|)(cy,cx) > 3.1  &&  disp(cy,cx) > 0.007
    // Centers are >= 11 px from every border, so no padding / zeroArea handling needed.
    float g = 0.0f;
    if (lane < 9) {
        const int dy = lane / 3 - 1;
        const int dx = lane % 3 - 1;
        const float* p = fch + (size_t)(cy + dy - 1) * WW + (cx + dx);
        const float a = p[1]  + 2.0f * p[WW + 1] + p[2 * WW + 1];
        const float b = p[-1] + 2.0f * p[WW - 1] + p[2 * WW - 1];
        g = fabsf(a - b);
    }
    #pragma unroll
    for (int o = 16; o; o >>= 1) g = fmaxf(g, __shfl_xor_sync(0xFFFFFFFFu, g, o));
    const float dC = dch[(size_t)cy * WW + cx];
    const bool validRow = (g > 3.1f) && (dC > 0.007f);

    // ---- gather 2000 samples into registers; bx/by reads are fully coalesced,
    // disp reads stay inside a 15x23 window -> L1/L2 resident.
    const int* bxp = bxs + (size_t)n * DENSE;
    const int* byp = bys + (size_t)n * DENSE;

    float sv[63];
    float mx = -1e30f, mn = 1e30f, stot = 0.0f;
    #pragma unroll
    for (int k = 0; k < 63; k++) {
        const int  j = lane + (k << 5);
        const bool v = (k < 62) || (j < DENSE);   // compile-time true for k<62
        float val = 0.0f;
        if (v) {
            const int sx = cx + bxp[j];
            const int sy = cy + byp[j];
            val = dch[(size_t)sy * WW + sx];
            mx = fmaxf(mx, val);
            mn = fminf(mn, val);
            stot += val;
        }
        sv[k] = val;
    }
    #pragma unroll
    for (int o = 16; o; o >>= 1) {
        mx   = fmaxf(mx, __shfl_xor_sync(0xFFFFFFFFu, mx, o));
        mn   = fminf(mn, __shfl_xor_sync(0xFFFFFFFFu, mn, o));
        stot +=          __shfl_xor_sync(0xFFFFFFFFu, stot, o);
    }

    // ---- 2-cluster k-means, 10 iterations.
    float kL = mx, kS = mn;
    float lastCnt = 0.0f;   // belongingLarge count of the FINAL iteration (reference semantics)
    #pragma unroll 1
    for (int it = 0; it < KMEAN; it++) {
        float sumL = 0.0f;
        float cntL = 0.0f;
        #pragma unroll
        for (int k = 0; k < 63; k++) {
            const bool v = (k < 62) || (lane < 16);
            if (v) {
                const float s  = sv[k];
                const float dl = fabsf(s - kL);
                const float ds = fabsf(s - kS);
                if (dl <= ds) { sumL += s; cntL += 1.0f; }
            }
        }
        #pragma unroll
        for (int o = 16; o; o >>= 1) {
            sumL += __shfl_xor_sync(0xFFFFFFFFu, sumL, o);
            cntL += __shfl_xor_sync(0xFFFFFFFFu, cntL, o);
        }
        kL = sumL / cntL;
        kS = (stot - sumL) / ((float)DENSE - cntL);
        lastCnt = cntL;
    }

    const bool keep = validRow && ((kL - kS) > 0.005f) && (lastCnt > 5.0f);
    if (lane == 0) {
        const float kf = keep ? 1.0f : 0.0f;
        out[2 * n]     = kL * kf;
        out[2 * n + 1] = kS * kf;
    }
}

extern "C" void kernel_launch(void* const* d_in, const int* in_sizes, int n_in,
                              void* d_out, int out_size)
{
    const float* disp = (const float*)d_in[0];
    const float* fore = (const float*)d_in[1];
    const int*   cxs  = (const int*)  d_in[2];
    const int*   cys  = (const int*)  d_in[3];
    const int*   bxs  = (const int*)  d_in[4];
    const int*   bys  = (const int*)  d_in[5];
    float*       out  = (float*)d_out;

    // 8 warps/block, warp per point -> 625 blocks
    const int threads = 256;
    const int blocks  = (NPTS * 32 + threads - 1) / threads;
    rsbsp_kernel<<<blocks, threads>>>(disp, fore, cxs, cys, bxs, bys, out);
}

// round 2
// speedup vs baseline: 2.9273x; 2.9273x over previous
#include <cuda_runtime.h>
#include <cuda_bf16.h>

#define BCH   10
#define HH    320
#define WW    1024
#define PTS   500
#define DENSE 2000
#define KMEAN 10
#define NPTS  (BCH * PTS)
#define CHUNKS (DENSE / 4)      // 500 int4 chunks per point

// One warp per center point. Samples live in registers (64 per lane, int4-gathered).
__global__ __launch_bounds__(128, 4)
void rsbsp_kernel(const float* __restrict__ disp,
                  const float* __restrict__ fore,
                  const int*   __restrict__ cxs,
                  const int*   __restrict__ cys,
                  const int*   __restrict__ bxs,
                  const int*   __restrict__ bys,
                  float*       __restrict__ out)
{
    const int gwarp = (blockIdx.x * blockDim.x + threadIdx.x) >> 5;
    const int lane  = threadIdx.x & 31;
    if (gwarp >= NPTS) return;

    const int n    = gwarp;
    const int chan = n / PTS;
    const int cx   = cxs[n];
    const int cy   = cys[n];
    const float* dch = disp + (size_t)chan * (HH * WW);
    const float* fch = fore + (size_t)chan * (HH * WW);

    // ---- validRow: maxpool3x3(|sobel_x(forepred)|)(cy,cx) > 3.1  &&  disp(cy,cx) > 0.007
    // Centers are >= 11 px from every border (zeroArea rows/cols never reached).
    float g = 0.0f;
    if (lane < 9) {
        const int dy = lane / 3 - 1;
        const int dx = lane % 3 - 1;
        const float* p = fch + (size_t)(cy + dy - 1) * WW + (cx + dx);
        const float a = p[1]  + 2.0f * p[WW + 1] + p[2 * WW + 1];
        const float b = p[-1] + 2.0f * p[WW - 1] + p[2 * WW - 1];
        g = fabsf(a - b);
    }
    #pragma unroll
    for (int o = 16; o; o >>= 1) g = fmaxf(g, __shfl_xor_sync(0xFFFFFFFFu, g, o));

    const int   base = (cy << 10) + cx;      // WW == 1024
    const float dC   = dch[base];

    if (!((g > 3.1f) && (dC > 0.007f))) {
        // keep == 0 regardless of k-means result -> skip ALL gather + k-means work.
        if (lane == 0) { out[2 * n] = 0.0f; out[2 * n + 1] = 0.0f; }
        return;
    }

    // ---- gather 2000 samples into registers via int4 loads of bx/by.
    // Chunk c handles samples [4c, 4c+4); lane l owns chunks l, l+32, ..., padded to 16.
    const int4* bx4p = (const int4*)(bxs + (size_t)n * DENSE);
    const int4* by4p = (const int4*)(bys + (size_t)n * DENSE);

    float sv[64];
    float mx = -1e30f, mn = 1e30f, stot = 0.0f;
    #pragma unroll
    for (int k = 0; k < 16; k++) {
        const int  c     = lane + (k << 5);
        const bool valid = (k < 15) || (c < CHUNKS);   // compile-time true for k<15
        float v0 = -1e30f, v1 = -1e30f, v2 = -1e30f, v3 = -1e30f;  // pad: never joins large cluster
        if (valid) {
            const int4 b4 = bx4p[c];
            const int4 y4 = by4p[c];
            v0 = dch[base + y4.x * WW + b4.x];
            v1 = dch[base + y4.y * WW + b4.y];
            v2 = dch[base + y4.z * WW + b4.z];
            v3 = dch[base + y4.w * WW + b4.w];
            mx = fmaxf(fmaxf(mx, v0), fmaxf(v1, fmaxf(v2, v3)));
            mn = fminf(fminf(mn, v0), fminf(v1, fminf(v2, v3)));
            stot += (v0 + v1) + (v2 + v3);
        }
        sv[4 * k + 0] = v0;
        sv[4 * k + 1] = v1;
        sv[4 * k + 2] = v2;
        sv[4 * k + 3] = v3;
    }
    #pragma unroll
    for (int o = 16; o; o >>= 1) {
        mx   = fmaxf(mx, __shfl_xor_sync(0xFFFFFFFFu, mx, o));
        mn   = fminf(mn, __shfl_xor_sync(0xFFFFFFFFu, mn, o));
        stot +=          __shfl_xor_sync(0xFFFFFFFFu, stot, o);
    }

    // ---- 2-cluster 1-D k-means. kL > kS, so |s-kL| <= |s-kS|  <=>  s >= (kL+kS)/2
    // (tie at midpoint -> large cluster, matching dl<=ds). Bitwise fixed point => all
    // remaining reference iterations are identical -> exact early exit.
    float kL = mx, kS = mn;
    float lastCnt = 0.0f;
    #pragma unroll 1
    for (int it = 0; it < KMEAN; it++) {
        const float mid = 0.5f * (kL + kS);
        float s0 = 0.0f, s1 = 0.0f, c0 = 0.0f, c1 = 0.0f;
        #pragma unroll
        for (int k = 0; k < 64; k += 2) {
            const float a = sv[k], b = sv[k + 1];
            if (a >= mid) { s0 += a; c0 += 1.0f; }
            if (b >= mid) { s1 += b; c1 += 1.0f; }
        }
        float sumL = s0 + s1;
        float cntL = c0 + c1;
        #pragma unroll
        for (int o = 16; o; o >>= 1) {
            sumL += __shfl_xor_sync(0xFFFFFFFFu, sumL, o);
            cntL += __shfl_xor_sync(0xFFFFFFFFu, cntL, o);
        }
        const float nkL = __fdividef(sumL, cntL);
        const float nkS = __fdividef(stot - sumL, (float)DENSE - cntL);
        lastCnt = cntL;
        const bool conv = (nkL == kL) && (nkS == kS);
        kL = nkL; kS = nkS;
        if (conv) break;
    }

    const bool keep = ((kL - kS) > 0.005f) && (lastCnt > 5.0f);
    if (lane == 0) {
        const float kf = keep ? 1.0f : 0.0f;
        out[2 * n]     = kL * kf;
        out[2 * n + 1] = kS * kf;
    }
}

extern "C" void kernel_launch(void* const* d_in, const int* in_sizes, int n_in,
                              void* d_out, int out_size)
{
    const float* disp = (const float*)d_in[0];
    const float* fore = (const float*)d_in[1];
    const int*   cxs  = (const int*)  d_in[2];
    const int*   cys  = (const int*)  d_in[3];
    const int*   bxs  = (const int*)  d_in[4];
    const int*   bys  = (const int*)  d_in[5];
    float*       out  = (float*)d_out;

    // 4 warps/block, warp per point -> 1250 blocks (finer retirement granularity
    // given the ~75% early-exit warps).
    const int threads = 128;
    const int blocks  = (NPTS * 32 + threads - 1) / threads;
    rsbsp_kernel<<<blocks, threads>>>(disp, fore, cxs, cys, bxs, bys, out);
}